// round 11
// baseline (speedup 1.0000x reference)
#include <cuda_runtime.h>

// ---------------------------------------------------------------------------
// EdgeNetwork: per-node factorization + lane-paired edge MLP.
//   pre_k : xs[n] = x[n]@W1a + b1 + vp[batch[n]]@W1c ; xb[n] = x[n]@W1b
//   edge_k: TWO LANES per edge (lane2i: ch0-3, lane2i+1: ch4-7). One LDG.128
//           per lane fetches half a 32B node record; the pair's accesses
//           coalesce into one L1 wavefront -> gather wavefronts halved.
//           LN stats and h-exchange via shfl.bfly(1). 2-edge ILP (A,B).
// ---------------------------------------------------------------------------

#define NODE_CAP 131072
#define KLOG2E 2.8853900817779268f   // 2*log2(e)
#define FULLMASK 0xffffffffu

__device__ __align__(16) float g_xs[NODE_CAP * 8];
__device__ __align__(16) float g_xb[NODE_CAP * 8];

__device__ __forceinline__ int detect_is64(const int* __restrict__ ei) {
    int nz = 0;
#pragma unroll
    for (int i = 1; i < 16; i += 2) nz |= ei[i];
    return nz == 0;
}

// ---------------------------------------------------------------------------
// Per-node precompute (unchanged, validated)
// ---------------------------------------------------------------------------
__global__ void __launch_bounds__(256) pre_k(
    const float* __restrict__ x, const int* __restrict__ batch_raw,
    const float* __restrict__ vp, const float* __restrict__ W1,
    const float* __restrict__ b1, const int* __restrict__ ei, int N, int G)
{
    __shared__ float sW1[48 * 8];
    __shared__ float svp[64 * 16];
    __shared__ float sb1[8];
    __shared__ int sflag;
    int t = threadIdx.x;
    if (t == 0) sflag = detect_is64(ei);
    for (int i = t; i < 384; i += blockDim.x) sW1[i] = W1[i];
    int gv = G * 16; if (gv > 1024) gv = 1024;
    for (int i = t; i < gv; i += blockDim.x) svp[i] = vp[i];
    if (t < 8) sb1[t] = b1[t];
    __syncthreads();

    int n = blockIdx.x * blockDim.x + t;
    if (n >= N) return;

    int g = sflag ? batch_raw[2 * n] : batch_raw[n];

    float xi[16];
    const float* xr = x + (size_t)n * 16;
#pragma unroll
    for (int k = 0; k < 16; k += 4) {
        float4 v = *(const float4*)(xr + k);
        xi[k] = v.x; xi[k + 1] = v.y; xi[k + 2] = v.z; xi[k + 3] = v.w;
    }
    const float* vg = svp + g * 16;

    float xs[8], xb[8];
#pragma unroll
    for (int j = 0; j < 8; j++) {
        float a = sb1[j];
        float b = 0.0f;
#pragma unroll
        for (int k = 0; k < 16; k++) {
            a = fmaf(xi[k], sW1[k * 8 + j], a);
            a = fmaf(vg[k], sW1[(32 + k) * 8 + j], a);
            b = fmaf(xi[k], sW1[(16 + k) * 8 + j], b);
        }
        xs[j] = a; xb[j] = b;
    }
    float4* o1 = (float4*)(g_xs + (size_t)n * 8);
    o1[0] = make_float4(xs[0], xs[1], xs[2], xs[3]);
    o1[1] = make_float4(xs[4], xs[5], xs[6], xs[7]);
    float4* o2 = (float4*)(g_xb + (size_t)n * 8);
    o2[0] = make_float4(xb[0], xb[1], xb[2], xb[3]);
    o2[1] = make_float4(xb[4], xb[5], xb[6], xb[7]);
}

// ---------------------------------------------------------------------------
// tanh(z2), z2 = 2*log2(e)*z : t = 1 - 2*rcp(ex2(z2)+1)
// ---------------------------------------------------------------------------
__device__ __forceinline__ float tanh_from_z2(float z2) {
    float q, rc;
    asm("ex2.approx.f32 %0, %1;" : "=f"(q) : "f"(z2));
    float sum = q + 1.0f;
    asm("rcp.approx.f32 %0, %1;" : "=f"(rc) : "f"(sum));
    return fmaf(-2.0f, rc, 1.0f);
}

// Pair LN stats: h[4] per lane, full stats over 8 via one bfly exchange.
__device__ __forceinline__ void ln_stats_pair(const float h[4], float& mu, float& P) {
    float s4 = (h[0] + h[1]) + (h[2] + h[3]);
    float q4 = fmaf(h[0], h[0], fmaf(h[1], h[1], fmaf(h[2], h[2], h[3] * h[3])));
    float s8 = s4 + __shfl_xor_sync(FULLMASK, s4, 1);
    float q8 = q4 + __shfl_xor_sync(FULLMASK, q4, 1);
    mu = s8 * 0.125f;
    float var = fmaf(-mu, mu, q8 * 0.125f);
    P = rsqrtf(var + 1e-5f) * KLOG2E;
}

// Uniform-affine LN + tanh on the lane's 4 channels (in place).
__device__ __forceinline__ void ln_tanh_u4(float h[4]) {
    float mu, P;
    ln_stats_pair(h, mu, P);
    float c = -mu * P;
#pragma unroll
    for (int j = 0; j < 4; j++)
        h[j] = tanh_from_z2(fmaf(h[j], P, c));
}

// General LN + tanh: g/kbe are the lane's half (4 values) from smem.
__device__ __forceinline__ void ln_tanh_g4(float h[4], const float* __restrict__ g,
                                           const float* __restrict__ kbe) {
    float mu, P;
    ln_stats_pair(h, mu, P);
#pragma unroll
    for (int j = 0; j < 4; j++) {
        float w = P * g[j];
        float c = fmaf(-mu, w, kbe[j]);
        h[j] = tanh_from_z2(fmaf(h[j], w, c));
    }
}

// Pair GEMM: out[j] = b[j] + sum_k h[k]*w_own[k][j] + sum_k p[k]*w_oth[k][j]
// where p = partner's h (4 shfls). w_own = rows of OWN half, w_oth = partner rows.
__device__ __forceinline__ void gemm_pair(
    const float h[4], float o[4],
    const float w_own[4][4], const float w_oth[4][4], const float b[4])
{
    float p0 = __shfl_xor_sync(FULLMASK, h[0], 1);
    float p1 = __shfl_xor_sync(FULLMASK, h[1], 1);
    float p2 = __shfl_xor_sync(FULLMASK, h[2], 1);
    float p3 = __shfl_xor_sync(FULLMASK, h[3], 1);
#pragma unroll
    for (int j = 0; j < 4; j++) {
        float a = b[j];
        a = fmaf(h[0], w_own[0][j], a);
        a = fmaf(h[1], w_own[1][j], a);
        a = fmaf(h[2], w_own[2][j], a);
        a = fmaf(h[3], w_own[3][j], a);
        a = fmaf(p0, w_oth[0][j], a);
        a = fmaf(p1, w_oth[1][j], a);
        a = fmaf(p2, w_oth[2][j], a);
        a = fmaf(p3, w_oth[3][j], a);
        o[j] = a;
    }
}

__global__ void __launch_bounds__(128, 4) edge_k(
    const int* __restrict__ ei, int E,
    const float* __restrict__ g1, const float* __restrict__ be1,
    const float* __restrict__ W2, const float* __restrict__ b2,
    const float* __restrict__ g2, const float* __restrict__ be2,
    const float* __restrict__ W3, const float* __restrict__ b3,
    const float* __restrict__ g3, const float* __restrict__ be3,
    const float* __restrict__ W4, const float* __restrict__ b4,
    float* __restrict__ out)
{
    __shared__ float sW2[64], sW3[64], sW4[8], sB2[8], sB3[8];
    __shared__ float sv[48];  // g1,kbe1,g2,kbe2,g3,kbe3 (general path)
    __shared__ float sb4;
    __shared__ int sflag, suni;
    int t = threadIdx.x;
    if (t == 0) {
        sflag = detect_is64(ei); sb4 = b4[0];
        int u = 1;
#pragma unroll
        for (int j = 0; j < 8; j++) {
            u &= (g1[j] == 1.0f) & (be1[j] == 0.0f);
            u &= (g2[j] == 1.0f) & (be2[j] == 0.0f);
            u &= (g3[j] == 1.0f) & (be3[j] == 0.0f);
        }
        suni = u;
    }
    if (t < 64) { sW2[t] = W2[t]; sW3[t] = W3[t]; }
    if (t < 8) {
        sW4[t] = W4[t]; sB2[t] = b2[t]; sB3[t] = b3[t];
        sv[t]      = g1[t];  sv[8 + t]  = KLOG2E * be1[t];
        sv[16 + t] = g2[t];  sv[24 + t] = KLOG2E * be2[t];
        sv[32 + t] = g3[t];  sv[40 + t] = KLOG2E * be3[t];
    }
    __syncthreads();

    const int lane = t & 31;
    const int half = lane & 1;       // 0: channels 0-3, 1: channels 4-7
    const int pairIdx = lane >> 1;   // 0..15: edge slot within warp
    const int hc = half * 4;         // channel offset of own half

    // Per-thread weight registers (own output-column half, split by row half).
    float w2_own[4][4], w2_oth[4][4], w3_own[4][4], w3_oth[4][4];
    float bs2[4], bs3[4], w4r[4];
#pragma unroll
    for (int k = 0; k < 4; k++)
#pragma unroll
        for (int j = 0; j < 4; j++) {
            w2_own[k][j] = sW2[(hc + k) * 8 + hc + j];
            w2_oth[k][j] = sW2[((4 - hc) + k) * 8 + hc + j];
            w3_own[k][j] = sW3[(hc + k) * 8 + hc + j];
            w3_oth[k][j] = sW3[((4 - hc) + k) * 8 + hc + j];
        }
#pragma unroll
    for (int j = 0; j < 4; j++) {
        bs2[j] = sB2[hc + j]; bs3[j] = sB3[hc + j]; w4r[j] = sW4[hc + j];
    }

    const int is64 = sflag;
    const int uni  = suni;
    const float b4s = sb4;
    const int gw = (blockIdx.x * blockDim.x + t) >> 5;          // global warp id
    const int nwarps = (gridDim.x * blockDim.x) >> 5;
    const int strideE = nwarps * 32;
    const int Em1 = E - 1;

    for (int base = gw * 32; base < E; base += strideE) {
        int eA = base + pairIdx;
        int eB = eA + 16;
        int eAc = eA < Em1 ? eA : Em1;   // clamped (safe garbage on tail)
        int eBc = eB < Em1 ? eB : Em1;

        int sA, dA, sB, dB;
        if (is64) {
            sA = ei[2 * (size_t)eAc];           dA = ei[2 * ((size_t)E + eAc)];
            sB = ei[2 * (size_t)eBc];           dB = ei[2 * ((size_t)E + eBc)];
        } else {
            sA = ei[eAc];                        dA = ei[(size_t)E + eAc];
            sB = ei[eBc];                        dB = ei[(size_t)E + eBc];
        }

        // One LDG.128 per array per edge-slot: lane pair covers the 32B record.
        float4 xsA = *((const float4*)(g_xs + (size_t)sA * 8) + half);
        float4 xbA = *((const float4*)(g_xb + (size_t)dA * 8) + half);
        float4 xsB = *((const float4*)(g_xs + (size_t)sB * 8) + half);
        float4 xbB = *((const float4*)(g_xb + (size_t)dB * 8) + half);

        float hA[4] = { xsA.x + xbA.x, xsA.y + xbA.y, xsA.z + xbA.z, xsA.w + xbA.w };
        float hB[4] = { xsB.x + xbB.x, xsB.y + xbB.y, xsB.z + xbB.z, xsB.w + xbB.w };

        float h2A[4], h2B[4], h3A[4], h3B[4];
        if (uni) {
            ln_tanh_u4(hA);                         ln_tanh_u4(hB);
            gemm_pair(hA, h2A, w2_own, w2_oth, bs2);
            gemm_pair(hB, h2B, w2_own, w2_oth, bs2);
            ln_tanh_u4(h2A);                        ln_tanh_u4(h2B);
            gemm_pair(h2A, h3A, w3_own, w3_oth, bs3);
            gemm_pair(h2B, h3B, w3_own, w3_oth, bs3);
            ln_tanh_u4(h3A);                        ln_tanh_u4(h3B);
        } else {
            ln_tanh_g4(hA, sv + hc, sv + 8 + hc);
            ln_tanh_g4(hB, sv + hc, sv + 8 + hc);
            gemm_pair(hA, h2A, w2_own, w2_oth, bs2);
            gemm_pair(hB, h2B, w2_own, w2_oth, bs2);
            ln_tanh_g4(h2A, sv + 16 + hc, sv + 24 + hc);
            ln_tanh_g4(h2B, sv + 16 + hc, sv + 24 + hc);
            gemm_pair(h2A, h3A, w3_own, w3_oth, bs3);
            gemm_pair(h2B, h3B, w3_own, w3_oth, bs3);
            ln_tanh_g4(h3A, sv + 32 + hc, sv + 40 + hc);
            ln_tanh_g4(h3B, sv + 32 + hc, sv + 40 + hc);
        }

        // Final dot: partial over own 4 channels + pair reduce.
        float pA = fmaf(h3A[0], w4r[0], fmaf(h3A[1], w4r[1],
                   fmaf(h3A[2], w4r[2], h3A[3] * w4r[3])));
        float pB = fmaf(h3B[0], w4r[0], fmaf(h3B[1], w4r[1],
                   fmaf(h3B[2], w4r[2], h3B[3] * w4r[3])));
        float oA = pA + __shfl_xor_sync(FULLMASK, pA, 1);
        float oB = pB + __shfl_xor_sync(FULLMASK, pB, 1);

        if (half == 0) {
            if (eA < E) out[eA] = b4s + oA;
            if (eB < E) out[eB] = b4s + oB;
        }
    }
}

// ---------------------------------------------------------------------------
extern "C" void kernel_launch(void* const* d_in, const int* in_sizes, int n_in,
                              void* d_out, int out_size)
{
    const float* x     = (const float*)d_in[0];
    const int*   ei    = (const int*)d_in[1];
    const float* vp    = (const float*)d_in[2];
    const int*   batch = (const int*)d_in[3];
    const float* W1  = (const float*)d_in[4];
    const float* b1  = (const float*)d_in[5];
    const float* g1  = (const float*)d_in[6];
    const float* be1 = (const float*)d_in[7];
    const float* W2  = (const float*)d_in[8];
    const float* b2  = (const float*)d_in[9];
    const float* g2  = (const float*)d_in[10];
    const float* be2 = (const float*)d_in[11];
    const float* W3  = (const float*)d_in[12];
    const float* b3  = (const float*)d_in[13];
    const float* g3  = (const float*)d_in[14];
    const float* be3 = (const float*)d_in[15];
    const float* W4  = (const float*)d_in[16];
    const float* b4  = (const float*)d_in[17];

    int N = in_sizes[0] / 16;
    int E = in_sizes[1] / 2;
    int G = in_sizes[2] / 16;

    int pb = (N + 255) / 256;
    pre_k<<<pb, 256>>>(x, batch, vp, W1, b1, ei, N, G);

    // persistent grid: 4 blocks/SM x 148 SMs, 128 threads
    int eb = 592;
    long long warps_needed = ((long long)E + 31) / 32;
    long long blocks_needed = (warps_needed + 3) / 4;
    if (blocks_needed < eb) eb = (int)(blocks_needed > 0 ? blocks_needed : 1);
    edge_k<<<eb, 128>>>(ei, E, g1, be1, W2, b2, g2, be2, W3, b3, g3, be3,
                        W4, b4, (float*)d_out);
}

// round 12
// speedup vs baseline: 1.1102x; 1.1102x over previous
#include <cuda_runtime.h>

// ---------------------------------------------------------------------------
// EdgeNetwork: per-node factorization + 3 edges/thread (scalar math).
//   pre_k : xs[n] = x[n]@W1a + b1 + vp[batch[n]]@W1c ; xb[n] = x[n]@W1b
//   edge_k: h = xs[s]+xb[d]; 3x(LN+tanh) H=8 in regs, K-folded tanh,
//           index prefetch, persistent grid, uniform-affine LN fast path.
//   R12: 3 independent edges per thread (A at e, B at e+NT, C at e+2NT) for
//        deeper ILP; layer-3 tanh folded into final dot (out = C - 2*rc.w4).
// ---------------------------------------------------------------------------

#define NODE_CAP 131072
#define KLOG2E 2.8853900817779268f   // 2*log2(e)

__device__ __align__(16) float g_xs[NODE_CAP * 8];
__device__ __align__(16) float g_xb[NODE_CAP * 8];

__device__ __forceinline__ int detect_is64(const int* __restrict__ ei) {
    int nz = 0;
#pragma unroll
    for (int i = 1; i < 16; i += 2) nz |= ei[i];
    return nz == 0;
}

// ---------------------------------------------------------------------------
// Per-node precompute (unchanged, validated)
// ---------------------------------------------------------------------------
__global__ void __launch_bounds__(256) pre_k(
    const float* __restrict__ x, const int* __restrict__ batch_raw,
    const float* __restrict__ vp, const float* __restrict__ W1,
    const float* __restrict__ b1, const int* __restrict__ ei, int N, int G)
{
    __shared__ float sW1[48 * 8];
    __shared__ float svp[64 * 16];
    __shared__ float sb1[8];
    __shared__ int sflag;
    int t = threadIdx.x;
    if (t == 0) sflag = detect_is64(ei);
    for (int i = t; i < 384; i += blockDim.x) sW1[i] = W1[i];
    int gv = G * 16; if (gv > 1024) gv = 1024;
    for (int i = t; i < gv; i += blockDim.x) svp[i] = vp[i];
    if (t < 8) sb1[t] = b1[t];
    __syncthreads();

    int n = blockIdx.x * blockDim.x + t;
    if (n >= N) return;

    int g = sflag ? batch_raw[2 * n] : batch_raw[n];

    float xi[16];
    const float* xr = x + (size_t)n * 16;
#pragma unroll
    for (int k = 0; k < 16; k += 4) {
        float4 v = *(const float4*)(xr + k);
        xi[k] = v.x; xi[k + 1] = v.y; xi[k + 2] = v.z; xi[k + 3] = v.w;
    }
    const float* vg = svp + g * 16;

    float xs[8], xb[8];
#pragma unroll
    for (int j = 0; j < 8; j++) {
        float a = sb1[j];
        float b = 0.0f;
#pragma unroll
        for (int k = 0; k < 16; k++) {
            a = fmaf(xi[k], sW1[k * 8 + j], a);
            a = fmaf(vg[k], sW1[(32 + k) * 8 + j], a);
            b = fmaf(xi[k], sW1[(16 + k) * 8 + j], b);
        }
        xs[j] = a; xb[j] = b;
    }
    float4* o1 = (float4*)(g_xs + (size_t)n * 8);
    o1[0] = make_float4(xs[0], xs[1], xs[2], xs[3]);
    o1[1] = make_float4(xs[4], xs[5], xs[6], xs[7]);
    float4* o2 = (float4*)(g_xb + (size_t)n * 8);
    o2[0] = make_float4(xb[0], xb[1], xb[2], xb[3]);
    o2[1] = make_float4(xb[4], xb[5], xb[6], xb[7]);
}

// ---------------------------------------------------------------------------
// tanh pieces: z2 = 2*log2(e)*z ; rc = rcp(ex2(z2)+1) ; tanh = 1 - 2*rc
// ---------------------------------------------------------------------------
__device__ __forceinline__ float rc_from_z2(float z2) {
    float q, rc;
    asm("ex2.approx.f32 %0, %1;" : "=f"(q) : "f"(z2));
    float sum = q + 1.0f;
    asm("rcp.approx.f32 %0, %1;" : "=f"(rc) : "f"(sum));
    return rc;
}
__device__ __forceinline__ float tanh_from_z2(float z2) {
    return fmaf(-2.0f, rc_from_z2(z2), 1.0f);
}

__device__ __forceinline__ void ln_stats(const float h[8], float& mu, float& P) {
    float s = ((h[0] + h[1]) + (h[2] + h[3])) + ((h[4] + h[5]) + (h[6] + h[7]));
    float ss = 0.0f;
#pragma unroll
    for (int j = 0; j < 8; j++) ss = fmaf(h[j], h[j], ss);
    mu = s * 0.125f;
    float var = fmaf(-mu, mu, ss * 0.125f);
    P = rsqrtf(var + 1e-5f) * KLOG2E;
}

// LN + tanh (uniform / general)
__device__ __forceinline__ void ln_tanh_u(float h[8]) {
    float mu, P; ln_stats(h, mu, P);
    float c = -mu * P;
#pragma unroll
    for (int j = 0; j < 8; j++) h[j] = tanh_from_z2(fmaf(h[j], P, c));
}
__device__ __forceinline__ void ln_tanh_g(float h[8], const float* __restrict__ g,
                                          const float* __restrict__ kbe) {
    float mu, P; ln_stats(h, mu, P);
#pragma unroll
    for (int j = 0; j < 8; j++) {
        float w = P * g[j];
        float c = fmaf(-mu, w, kbe[j]);
        h[j] = tanh_from_z2(fmaf(h[j], w, c));
    }
}

// LN + rc only (layer 3: tanh folded into final dot). Writes rc[8].
__device__ __forceinline__ void ln_rc_u(const float h[8], float rc[8]) {
    float mu, P; ln_stats(h, mu, P);
    float c = -mu * P;
#pragma unroll
    for (int j = 0; j < 8; j++) rc[j] = rc_from_z2(fmaf(h[j], P, c));
}
__device__ __forceinline__ void ln_rc_g(const float h[8], float rc[8],
                                        const float* __restrict__ g,
                                        const float* __restrict__ kbe) {
    float mu, P; ln_stats(h, mu, P);
#pragma unroll
    for (int j = 0; j < 8; j++) {
        float w = P * g[j];
        float c = fmaf(-mu, w, kbe[j]);
        rc[j] = rc_from_z2(fmaf(h[j], w, c));
    }
}

__device__ __forceinline__ void gemm8(const float hin[8], float hout[8],
                                      const float* __restrict__ W,
                                      const float* __restrict__ b) {
#pragma unroll
    for (int j = 0; j < 8; j++) {
        float a = b[j];
#pragma unroll
        for (int k = 0; k < 8; k++) a = fmaf(hin[k], W[k * 8 + j], a);
        hout[j] = a;
    }
}

// Gather node records and build h (one edge).
__device__ __forceinline__ void gather_h(int s, int d, float h[8]) {
    const float4* ap = (const float4*)(g_xs + (size_t)s * 8);
    const float4* bp = (const float4*)(g_xb + (size_t)d * 8);
    float4 a0 = ap[0], a1 = ap[1], c0 = bp[0], c1 = bp[1];
    h[0] = a0.x + c0.x; h[1] = a0.y + c0.y; h[2] = a0.z + c0.z; h[3] = a0.w + c0.w;
    h[4] = a1.x + c1.x; h[5] = a1.y + c1.y; h[6] = a1.z + c1.z; h[7] = a1.w + c1.w;
}

__device__ __forceinline__ void load_sd(const int* __restrict__ ei, size_t E,
                                        int e, int is64, int& s, int& d) {
    if (is64) { s = ei[2 * (size_t)e]; d = ei[2 * (E + (size_t)e)]; }
    else      { s = ei[e];             d = ei[E + (size_t)e]; }
}

__global__ void __launch_bounds__(128, 3) edge_k(
    const int* __restrict__ ei, int E,
    const float* __restrict__ g1, const float* __restrict__ be1,
    const float* __restrict__ W2, const float* __restrict__ b2,
    const float* __restrict__ g2, const float* __restrict__ be2,
    const float* __restrict__ W3, const float* __restrict__ b3,
    const float* __restrict__ g3, const float* __restrict__ be3,
    const float* __restrict__ W4, const float* __restrict__ b4,
    float* __restrict__ out)
{
    __shared__ float sW2[64], sW3[64], sW4[8];
    __shared__ float sv[64];  // g1,kbe1,b2,g2,kbe2,b3,g3,kbe3
    __shared__ float sW4sum;  // b4 + sum(W4)
    __shared__ int sflag, suni;
    int t = threadIdx.x;
    if (t == 0) {
        sflag = detect_is64(ei);
        float ssum = b4[0];
#pragma unroll
        for (int j = 0; j < 8; j++) ssum += W4[j];
        sW4sum = ssum;
        int u = 1;
#pragma unroll
        for (int j = 0; j < 8; j++) {
            u &= (g1[j] == 1.0f) & (be1[j] == 0.0f);
            u &= (g2[j] == 1.0f) & (be2[j] == 0.0f);
            u &= (g3[j] == 1.0f) & (be3[j] == 0.0f);
        }
        suni = u;
    }
    if (t < 64) { sW2[t] = W2[t]; sW3[t] = W3[t]; }
    if (t < 8) {
        sW4[t] = W4[t];
        sv[t]      = g1[t];  sv[8 + t]  = KLOG2E * be1[t];
        sv[16 + t] = b2[t];  sv[24 + t] = g2[t];  sv[32 + t] = KLOG2E * be2[t];
        sv[40 + t] = b3[t];  sv[48 + t] = g3[t];  sv[56 + t] = KLOG2E * be3[t];
    }
    __syncthreads();

    const float* sg1 = sv;       const float* skb1 = sv + 8;
    const float* sb2 = sv + 16;  const float* sg2  = sv + 24; const float* skb2 = sv + 32;
    const float* sb3 = sv + 40;  const float* sg3  = sv + 48; const float* skb3 = sv + 56;

    const int is64 = sflag;
    const int uni  = suni;
    const float w4sum = sW4sum;
    const int tid = blockIdx.x * blockDim.x + t;
    const int NT = gridDim.x * blockDim.x;
    const int chunk = 3 * NT;
    const int Em1 = E - 1;

    // first-iteration index prefetch (clamped loads are safe; stores predicated)
    int sA, dA, sB, dB, sC, dC;
    {
        int eA = tid;
        if (eA < E) {
            int eB = eA + NT, eC = eA + 2 * NT;
            load_sd(ei, (size_t)E, eA, is64, sA, dA);
            load_sd(ei, (size_t)E, eB < E ? eB : Em1, is64, sB, dB);
            load_sd(ei, (size_t)E, eC < E ? eC : Em1, is64, sC, dC);
        }
    }

    for (int eA = tid; eA < E; eA += chunk) {
        int eB = eA + NT, eC = eA + 2 * NT;

        // prefetch next chunk's indices
        int nsA = 0, ndA = 0, nsB = 0, ndB = 0, nsC = 0, ndC = 0;
        int eAn = eA + chunk;
        if (eAn < E) {
            int eBn = eAn + NT, eCn = eAn + 2 * NT;
            load_sd(ei, (size_t)E, eAn, is64, nsA, ndA);
            load_sd(ei, (size_t)E, eBn < E ? eBn : Em1, is64, nsB, ndB);
            load_sd(ei, (size_t)E, eCn < E ? eCn : Em1, is64, nsC, ndC);
        }

        float hA[8], hB[8], hC[8];
        gather_h(sA, dA, hA);
        gather_h(sB, dB, hB);
        gather_h(sC, dC, hC);

        float h2A[8], h2B[8], h2C[8], h3A[8], h3B[8], h3C[8];
        float rcA[8], rcB[8], rcC[8];
        if (uni) {
            ln_tanh_u(hA);  ln_tanh_u(hB);  ln_tanh_u(hC);
            gemm8(hA, h2A, sW2, sb2); gemm8(hB, h2B, sW2, sb2); gemm8(hC, h2C, sW2, sb2);
            ln_tanh_u(h2A); ln_tanh_u(h2B); ln_tanh_u(h2C);
            gemm8(h2A, h3A, sW3, sb3); gemm8(h2B, h3B, sW3, sb3); gemm8(h2C, h3C, sW3, sb3);
            ln_rc_u(h3A, rcA); ln_rc_u(h3B, rcB); ln_rc_u(h3C, rcC);
        } else {
            ln_tanh_g(hA, sg1, skb1);  ln_tanh_g(hB, sg1, skb1);  ln_tanh_g(hC, sg1, skb1);
            gemm8(hA, h2A, sW2, sb2); gemm8(hB, h2B, sW2, sb2); gemm8(hC, h2C, sW2, sb2);
            ln_tanh_g(h2A, sg2, skb2); ln_tanh_g(h2B, sg2, skb2); ln_tanh_g(h2C, sg2, skb2);
            gemm8(h2A, h3A, sW3, sb3); gemm8(h2B, h3B, sW3, sb3); gemm8(h2C, h3C, sW3, sb3);
            ln_rc_g(h3A, rcA, sg3, skb3); ln_rc_g(h3B, rcB, sg3, skb3); ln_rc_g(h3C, rcC, sg3, skb3);
        }

        // out = (b4 + sum(W4)) - 2 * sum_j rc_j * W4_j
        float dA4 = 0.0f, dB4 = 0.0f, dC4 = 0.0f;
#pragma unroll
        for (int k = 0; k < 8; k++) {
            float w = sW4[k];
            dA4 = fmaf(rcA[k], w, dA4);
            dB4 = fmaf(rcB[k], w, dB4);
            dC4 = fmaf(rcC[k], w, dC4);
        }
        out[eA] = fmaf(-2.0f, dA4, w4sum);
        if (eB < E) out[eB] = fmaf(-2.0f, dB4, w4sum);
        if (eC < E) out[eC] = fmaf(-2.0f, dC4, w4sum);

        sA = nsA; dA = ndA; sB = nsB; dB = ndB; sC = nsC; dC = ndC;
    }
}

// ---------------------------------------------------------------------------
extern "C" void kernel_launch(void* const* d_in, const int* in_sizes, int n_in,
                              void* d_out, int out_size)
{
    const float* x     = (const float*)d_in[0];
    const int*   ei    = (const int*)d_in[1];
    const float* vp    = (const float*)d_in[2];
    const int*   batch = (const int*)d_in[3];
    const float* W1  = (const float*)d_in[4];
    const float* b1  = (const float*)d_in[5];
    const float* g1  = (const float*)d_in[6];
    const float* be1 = (const float*)d_in[7];
    const float* W2  = (const float*)d_in[8];
    const float* b2  = (const float*)d_in[9];
    const float* g2  = (const float*)d_in[10];
    const float* be2 = (const float*)d_in[11];
    const float* W3  = (const float*)d_in[12];
    const float* b3  = (const float*)d_in[13];
    const float* g3  = (const float*)d_in[14];
    const float* be3 = (const float*)d_in[15];
    const float* W4  = (const float*)d_in[16];
    const float* b4  = (const float*)d_in[17];

    int N = in_sizes[0] / 16;
    int E = in_sizes[1] / 2;
    int G = in_sizes[2] / 16;

    int pb = (N + 255) / 256;
    pre_k<<<pb, 256>>>(x, batch, vp, W1, b1, ei, N, G);

    // persistent 1-wave grid: 3 blocks/SM x 148 SMs, 128 threads, 3 edges/thread
    int eb = 444;
    long long need = ((long long)E + 3LL * 128 - 1) / (3LL * 128);
    if (need < eb) eb = (int)(need > 0 ? need : 1);
    edge_k<<<eb, 128>>>(ei, E, g1, be1, W2, b2, g2, be2, W3, b3, g3, be3,
                        W4, b4, (float*)d_out);
}

// round 13
// speedup vs baseline: 1.1656x; 1.0499x over previous
#include <cuda_runtime.h>

// ---------------------------------------------------------------------------
// EdgeNetwork: per-node factorization + 2 edges/thread (scalar math).
//   pre_k : xs[n] = x[n]@W1a + b1 + vp[batch[n]]@W1c ; xb[n] = x[n]@W1b
//   edge_k: h = xs[s]+xb[d]; 3x(LN+tanh) H=8 in regs, K-folded tanh,
//           index prefetch, persistent grid, uniform-affine LN fast path.
//   R13: layer-3 tanh folded into final dot (out = w4sum - 2*rc.w4);
//        (128,5): cap 102 > natural 95 regs -> 20 warps/SM, grid 740.
// ---------------------------------------------------------------------------

#define NODE_CAP 131072
#define KLOG2E 2.8853900817779268f   // 2*log2(e)

__device__ __align__(16) float g_xs[NODE_CAP * 8];
__device__ __align__(16) float g_xb[NODE_CAP * 8];

__device__ __forceinline__ int detect_is64(const int* __restrict__ ei) {
    int nz = 0;
#pragma unroll
    for (int i = 1; i < 16; i += 2) nz |= ei[i];
    return nz == 0;
}

// ---------------------------------------------------------------------------
// Per-node precompute (unchanged, validated)
// ---------------------------------------------------------------------------
__global__ void __launch_bounds__(256) pre_k(
    const float* __restrict__ x, const int* __restrict__ batch_raw,
    const float* __restrict__ vp, const float* __restrict__ W1,
    const float* __restrict__ b1, const int* __restrict__ ei, int N, int G)
{
    __shared__ float sW1[48 * 8];
    __shared__ float svp[64 * 16];
    __shared__ float sb1[8];
    __shared__ int sflag;
    int t = threadIdx.x;
    if (t == 0) sflag = detect_is64(ei);
    for (int i = t; i < 384; i += blockDim.x) sW1[i] = W1[i];
    int gv = G * 16; if (gv > 1024) gv = 1024;
    for (int i = t; i < gv; i += blockDim.x) svp[i] = vp[i];
    if (t < 8) sb1[t] = b1[t];
    __syncthreads();

    int n = blockIdx.x * blockDim.x + t;
    if (n >= N) return;

    int g = sflag ? batch_raw[2 * n] : batch_raw[n];

    float xi[16];
    const float* xr = x + (size_t)n * 16;
#pragma unroll
    for (int k = 0; k < 16; k += 4) {
        float4 v = *(const float4*)(xr + k);
        xi[k] = v.x; xi[k + 1] = v.y; xi[k + 2] = v.z; xi[k + 3] = v.w;
    }
    const float* vg = svp + g * 16;

    float xs[8], xb[8];
#pragma unroll
    for (int j = 0; j < 8; j++) {
        float a = sb1[j];
        float b = 0.0f;
#pragma unroll
        for (int k = 0; k < 16; k++) {
            a = fmaf(xi[k], sW1[k * 8 + j], a);
            a = fmaf(vg[k], sW1[(32 + k) * 8 + j], a);
            b = fmaf(xi[k], sW1[(16 + k) * 8 + j], b);
        }
        xs[j] = a; xb[j] = b;
    }
    float4* o1 = (float4*)(g_xs + (size_t)n * 8);
    o1[0] = make_float4(xs[0], xs[1], xs[2], xs[3]);
    o1[1] = make_float4(xs[4], xs[5], xs[6], xs[7]);
    float4* o2 = (float4*)(g_xb + (size_t)n * 8);
    o2[0] = make_float4(xb[0], xb[1], xb[2], xb[3]);
    o2[1] = make_float4(xb[4], xb[5], xb[6], xb[7]);
}

// ---------------------------------------------------------------------------
// tanh pieces: z2 = 2*log2(e)*z ; rc = rcp(ex2(z2)+1) ; tanh = 1 - 2*rc
// ---------------------------------------------------------------------------
__device__ __forceinline__ float rc_from_z2(float z2) {
    float q, rc;
    asm("ex2.approx.f32 %0, %1;" : "=f"(q) : "f"(z2));
    float sum = q + 1.0f;
    asm("rcp.approx.f32 %0, %1;" : "=f"(rc) : "f"(sum));
    return rc;
}
__device__ __forceinline__ float tanh_from_z2(float z2) {
    return fmaf(-2.0f, rc_from_z2(z2), 1.0f);
}

__device__ __forceinline__ void ln_stats(const float h[8], float& mu, float& P) {
    float s = ((h[0] + h[1]) + (h[2] + h[3])) + ((h[4] + h[5]) + (h[6] + h[7]));
    float ss = 0.0f;
#pragma unroll
    for (int j = 0; j < 8; j++) ss = fmaf(h[j], h[j], ss);
    mu = s * 0.125f;
    float var = fmaf(-mu, mu, ss * 0.125f);
    P = rsqrtf(var + 1e-5f) * KLOG2E;
}

// LN + tanh (uniform / general), in place.
__device__ __forceinline__ void ln_tanh_u(float h[8]) {
    float mu, P; ln_stats(h, mu, P);
    float c = -mu * P;
#pragma unroll
    for (int j = 0; j < 8; j++) h[j] = tanh_from_z2(fmaf(h[j], P, c));
}
__device__ __forceinline__ void ln_tanh_g(float h[8], const float* __restrict__ g,
                                          const float* __restrict__ kbe) {
    float mu, P; ln_stats(h, mu, P);
#pragma unroll
    for (int j = 0; j < 8; j++) {
        float w = P * g[j];
        float c = fmaf(-mu, w, kbe[j]);
        h[j] = tanh_from_z2(fmaf(h[j], w, c));
    }
}

// LN + rc only (layer 3: tanh folded into the final dot). In place.
__device__ __forceinline__ void ln_rc_u(float h[8]) {
    float mu, P; ln_stats(h, mu, P);
    float c = -mu * P;
#pragma unroll
    for (int j = 0; j < 8; j++) h[j] = rc_from_z2(fmaf(h[j], P, c));
}
__device__ __forceinline__ void ln_rc_g(float h[8], const float* __restrict__ g,
                                        const float* __restrict__ kbe) {
    float mu, P; ln_stats(h, mu, P);
#pragma unroll
    for (int j = 0; j < 8; j++) {
        float w = P * g[j];
        float c = fmaf(-mu, w, kbe[j]);
        h[j] = rc_from_z2(fmaf(h[j], w, c));
    }
}

__device__ __forceinline__ void gemm8(const float hin[8], float hout[8],
                                      const float* __restrict__ W,
                                      const float* __restrict__ b) {
#pragma unroll
    for (int j = 0; j < 8; j++) {
        float a = b[j];
#pragma unroll
        for (int k = 0; k < 8; k++) a = fmaf(hin[k], W[k * 8 + j], a);
        hout[j] = a;
    }
}

__device__ __forceinline__ void load_idx(
    const int* __restrict__ ei, size_t E, int e0, int is64,
    int& s0, int& s1, int& d0, int& d1)
{
    if (is64) {
        int4 sw = *(const int4*)(ei + 2 * (size_t)e0);
        int4 dw = *(const int4*)(ei + 2 * (E + (size_t)e0));
        s0 = sw.x; s1 = sw.z; d0 = dw.x; d1 = dw.z;
    } else {
        int2 sw = *(const int2*)(ei + e0);
        int2 dw = *(const int2*)(ei + E + (size_t)e0);
        s0 = sw.x; s1 = sw.y; d0 = dw.x; d1 = dw.y;
    }
}

__global__ void __launch_bounds__(128, 5) edge_k(
    const int* __restrict__ ei, int E,
    const float* __restrict__ g1, const float* __restrict__ be1,
    const float* __restrict__ W2, const float* __restrict__ b2,
    const float* __restrict__ g2, const float* __restrict__ be2,
    const float* __restrict__ W3, const float* __restrict__ b3,
    const float* __restrict__ g3, const float* __restrict__ be3,
    const float* __restrict__ W4, const float* __restrict__ b4,
    float* __restrict__ out)
{
    __shared__ float sW2[64], sW3[64], sW4[8];
    __shared__ float sv[64];  // g1,kbe1,b2,g2,kbe2,b3,g3,kbe3
    __shared__ float sW4sum;  // b4 + sum(W4)
    __shared__ int sflag, suni;
    int t = threadIdx.x;
    if (t == 0) {
        sflag = detect_is64(ei);
        float ssum = b4[0];
#pragma unroll
        for (int j = 0; j < 8; j++) ssum += W4[j];
        sW4sum = ssum;
        int u = 1;
#pragma unroll
        for (int j = 0; j < 8; j++) {
            u &= (g1[j] == 1.0f) & (be1[j] == 0.0f);
            u &= (g2[j] == 1.0f) & (be2[j] == 0.0f);
            u &= (g3[j] == 1.0f) & (be3[j] == 0.0f);
        }
        suni = u;
    }
    if (t < 64) { sW2[t] = W2[t]; sW3[t] = W3[t]; }
    if (t < 8) {
        sW4[t] = W4[t];
        sv[t]      = g1[t];  sv[8 + t]  = KLOG2E * be1[t];
        sv[16 + t] = b2[t];  sv[24 + t] = g2[t];  sv[32 + t] = KLOG2E * be2[t];
        sv[40 + t] = b3[t];  sv[48 + t] = g3[t];  sv[56 + t] = KLOG2E * be3[t];
    }
    __syncthreads();

    const float* sg1 = sv;       const float* skb1 = sv + 8;
    const float* sb2 = sv + 16;  const float* sg2  = sv + 24; const float* skb2 = sv + 32;
    const float* sb3 = sv + 40;  const float* sg3  = sv + 48; const float* skb3 = sv + 56;

    const int is64 = sflag;
    const int uni  = suni;
    const float w4sum = sW4sum;
    const int stride2 = gridDim.x * blockDim.x * 2;
    int e0 = (blockIdx.x * blockDim.x + t) * 2;

    int s0 = 0, s1 = 0, d0 = 0, d1 = 0;
    bool pv = (e0 + 1 < E);
    if (pv) load_idx(ei, (size_t)E, e0, is64, s0, s1, d0, d1);

    while (e0 < E) {
        int e1 = e0 + stride2;
        if (pv) {
            int ns0 = 0, ns1 = 0, nd0 = 0, nd1 = 0;
            bool npv = (e1 + 1 < E);
            if (npv) load_idx(ei, (size_t)E, e1, is64, ns0, ns1, nd0, nd1);

            const float4* apA = (const float4*)(g_xs + (size_t)s0 * 8);
            const float4* bpA = (const float4*)(g_xb + (size_t)d0 * 8);
            const float4* apB = (const float4*)(g_xs + (size_t)s1 * 8);
            const float4* bpB = (const float4*)(g_xb + (size_t)d1 * 8);
            float4 a0A = apA[0], a1A = apA[1], c0A = bpA[0], c1A = bpA[1];
            float4 a0B = apB[0], a1B = apB[1], c0B = bpB[0], c1B = bpB[1];

            float hA[8] = { a0A.x + c0A.x, a0A.y + c0A.y, a0A.z + c0A.z, a0A.w + c0A.w,
                            a1A.x + c1A.x, a1A.y + c1A.y, a1A.z + c1A.z, a1A.w + c1A.w };
            float hB[8] = { a0B.x + c0B.x, a0B.y + c0B.y, a0B.z + c0B.z, a0B.w + c0B.w,
                            a1B.x + c1B.x, a1B.y + c1B.y, a1B.z + c1B.z, a1B.w + c1B.w };

            float h2A[8], h2B[8], h3A[8], h3B[8];
            if (uni) {
                ln_tanh_u(hA);                    ln_tanh_u(hB);
                gemm8(hA, h2A, sW2, sb2);         gemm8(hB, h2B, sW2, sb2);
                ln_tanh_u(h2A);                   ln_tanh_u(h2B);
                gemm8(h2A, h3A, sW3, sb3);        gemm8(h2B, h3B, sW3, sb3);
                ln_rc_u(h3A);                     ln_rc_u(h3B);
            } else {
                ln_tanh_g(hA, sg1, skb1);         ln_tanh_g(hB, sg1, skb1);
                gemm8(hA, h2A, sW2, sb2);         gemm8(hB, h2B, sW2, sb2);
                ln_tanh_g(h2A, sg2, skb2);        ln_tanh_g(h2B, sg2, skb2);
                gemm8(h2A, h3A, sW3, sb3);        gemm8(h2B, h3B, sW3, sb3);
                ln_rc_g(h3A, sg3, skb3);          ln_rc_g(h3B, sg3, skb3);
            }

            // out = (b4 + sum(W4)) - 2 * sum_j rc_j * W4_j
            float dA = 0.0f, dB = 0.0f;
#pragma unroll
            for (int k = 0; k < 8; k++) {
                float w = sW4[k];
                dA = fmaf(h3A[k], w, dA);
                dB = fmaf(h3B[k], w, dB);
            }
            float oA = fmaf(-2.0f, dA, w4sum);
            float oB = fmaf(-2.0f, dB, w4sum);
            *(float2*)(out + e0) = make_float2(oA, oB);

            s0 = ns0; s1 = ns1; d0 = nd0; d1 = nd1;
            pv = npv;
        } else {
            // scalar tail (e0 == E-1, only when E is odd)
            int s, d;
            if (is64) { s = ei[2 * (size_t)e0]; d = ei[2 * ((size_t)E + e0)]; }
            else      { s = ei[e0];             d = ei[(size_t)E + e0]; }
            const float4* ap = (const float4*)(g_xs + (size_t)s * 8);
            const float4* bp = (const float4*)(g_xb + (size_t)d * 8);
            float4 a0 = ap[0], a1 = ap[1], c0 = bp[0], c1 = bp[1];
            float h[8] = { a0.x + c0.x, a0.y + c0.y, a0.z + c0.z, a0.w + c0.w,
                           a1.x + c1.x, a1.y + c1.y, a1.z + c1.z, a1.w + c1.w };
            float h2[8], h3[8];
            if (uni) {
                ln_tanh_u(h);
                gemm8(h, h2, sW2, sb2);
                ln_tanh_u(h2);
                gemm8(h2, h3, sW3, sb3);
                ln_rc_u(h3);
            } else {
                ln_tanh_g(h, sg1, skb1);
                gemm8(h, h2, sW2, sb2);
                ln_tanh_g(h2, sg2, skb2);
                gemm8(h2, h3, sW3, sb3);
                ln_rc_g(h3, sg3, skb3);
            }
            float dd = 0.0f;
#pragma unroll
            for (int k = 0; k < 8; k++) dd = fmaf(h3[k], sW4[k], dd);
            out[e0] = fmaf(-2.0f, dd, w4sum);
            pv = (e1 + 1 < E);
            if (pv) load_idx(ei, (size_t)E, e1, is64, s0, s1, d0, d1);
        }
        e0 = e1;
    }
}

// ---------------------------------------------------------------------------
extern "C" void kernel_launch(void* const* d_in, const int* in_sizes, int n_in,
                              void* d_out, int out_size)
{
    const float* x     = (const float*)d_in[0];
    const int*   ei    = (const int*)d_in[1];
    const float* vp    = (const float*)d_in[2];
    const int*   batch = (const int*)d_in[3];
    const float* W1  = (const float*)d_in[4];
    const float* b1  = (const float*)d_in[5];
    const float* g1  = (const float*)d_in[6];
    const float* be1 = (const float*)d_in[7];
    const float* W2  = (const float*)d_in[8];
    const float* b2  = (const float*)d_in[9];
    const float* g2  = (const float*)d_in[10];
    const float* be2 = (const float*)d_in[11];
    const float* W3  = (const float*)d_in[12];
    const float* b3  = (const float*)d_in[13];
    const float* g3  = (const float*)d_in[14];
    const float* be3 = (const float*)d_in[15];
    const float* W4  = (const float*)d_in[16];
    const float* b4  = (const float*)d_in[17];

    int N = in_sizes[0] / 16;
    int E = in_sizes[1] / 2;
    int G = in_sizes[2] / 16;

    int pb = (N + 255) / 256;
    pre_k<<<pb, 256>>>(x, batch, vp, W1, b1, ei, N, G);

    // persistent 1-wave grid: 5 blocks/SM x 148 SMs = 20 warps/SM
    int eb = 740;
    long long need = ((long long)E / 2 + 127) / 128;
    if (need < eb) eb = (int)(need > 0 ? need : 1);
    edge_k<<<eb, 128>>>(ei, E, g1, be1, W2, b2, g2, be2, W3, b3, g3, be3,
                        W4, b4, (float*)d_out);
}

// round 14
// speedup vs baseline: 1.2121x; 1.0399x over previous
#include <cuda_runtime.h>

// ---------------------------------------------------------------------------
// EdgeNetwork: per-node factorization + 2 edges/thread (scalar math).
//   pre_k : xs[n] = center(x@W1a + b1 + vp[batch]@W1c); xb[n] = center(x@W1b)
//   edge_k: h = xs[s]+xb[d]; 3x(LN+tanh) H=8 in regs; MEAN-FREE LayerNorm:
//           W2/W3/b2/b3 are channel-centered at init so every LN input has
//           exactly zero channel-mean => LN = rsqrt(sumsq/8+eps) only.
//   Validated: K-folded tanh, layer-3 rc-fold, index prefetch, persistent
//              grid 740 x (128,5), uniform-affine fast path.
// ---------------------------------------------------------------------------

#define NODE_CAP 131072
#define KLOG2E 2.8853900817779268f   // 2*log2(e)

__device__ __align__(16) float g_xs[NODE_CAP * 8];
__device__ __align__(16) float g_xb[NODE_CAP * 8];

__device__ __forceinline__ int detect_is64(const int* __restrict__ ei) {
    int nz = 0;
#pragma unroll
    for (int i = 1; i < 16; i += 2) nz |= ei[i];
    return nz == 0;
}

// ---------------------------------------------------------------------------
// Per-node precompute; xs/xb stored mean-centered (LN is shift-invariant).
// ---------------------------------------------------------------------------
__global__ void __launch_bounds__(256) pre_k(
    const float* __restrict__ x, const int* __restrict__ batch_raw,
    const float* __restrict__ vp, const float* __restrict__ W1,
    const float* __restrict__ b1, const int* __restrict__ ei, int N, int G)
{
    __shared__ float sW1[48 * 8];
    __shared__ float svp[64 * 16];
    __shared__ float sb1[8];
    __shared__ int sflag;
    int t = threadIdx.x;
    if (t == 0) sflag = detect_is64(ei);
    for (int i = t; i < 384; i += blockDim.x) sW1[i] = W1[i];
    int gv = G * 16; if (gv > 1024) gv = 1024;
    for (int i = t; i < gv; i += blockDim.x) svp[i] = vp[i];
    if (t < 8) sb1[t] = b1[t];
    __syncthreads();

    int n = blockIdx.x * blockDim.x + t;
    if (n >= N) return;

    int g = sflag ? batch_raw[2 * n] : batch_raw[n];

    float xi[16];
    const float* xr = x + (size_t)n * 16;
#pragma unroll
    for (int k = 0; k < 16; k += 4) {
        float4 v = *(const float4*)(xr + k);
        xi[k] = v.x; xi[k + 1] = v.y; xi[k + 2] = v.z; xi[k + 3] = v.w;
    }
    const float* vg = svp + g * 16;

    float xs[8], xb[8];
#pragma unroll
    for (int j = 0; j < 8; j++) {
        float a = sb1[j];
        float b = 0.0f;
#pragma unroll
        for (int k = 0; k < 16; k++) {
            a = fmaf(xi[k], sW1[k * 8 + j], a);
            a = fmaf(vg[k], sW1[(32 + k) * 8 + j], a);
            b = fmaf(xi[k], sW1[(16 + k) * 8 + j], b);
        }
        xs[j] = a; xb[j] = b;
    }
    // center both records (mean of xs[s]+xb[d] = mean(xs)+mean(xb))
    float ms = 0.0f, mb = 0.0f;
#pragma unroll
    for (int j = 0; j < 8; j++) { ms += xs[j]; mb += xb[j]; }
    ms *= 0.125f; mb *= 0.125f;
#pragma unroll
    for (int j = 0; j < 8; j++) { xs[j] -= ms; xb[j] -= mb; }

    float4* o1 = (float4*)(g_xs + (size_t)n * 8);
    o1[0] = make_float4(xs[0], xs[1], xs[2], xs[3]);
    o1[1] = make_float4(xs[4], xs[5], xs[6], xs[7]);
    float4* o2 = (float4*)(g_xb + (size_t)n * 8);
    o2[0] = make_float4(xb[0], xb[1], xb[2], xb[3]);
    o2[1] = make_float4(xb[4], xb[5], xb[6], xb[7]);
}

// ---------------------------------------------------------------------------
// tanh pieces: z2 = 2*log2(e)*z ; rc = rcp(ex2(z2)+1) ; tanh = 1 - 2*rc
// ---------------------------------------------------------------------------
__device__ __forceinline__ float rc_from_z2(float z2) {
    float q, rc;
    asm("ex2.approx.f32 %0, %1;" : "=f"(q) : "f"(z2));
    float sum = q + 1.0f;
    asm("rcp.approx.f32 %0, %1;" : "=f"(rc) : "f"(sum));
    return rc;
}
__device__ __forceinline__ float tanh_from_z2(float z2) {
    return fmaf(-2.0f, rc_from_z2(z2), 1.0f);
}

// Mean-free LN scale: inputs have zero channel-mean by construction.
// P = rsqrt(sumsq/8 + eps) * 2*log2(e)
__device__ __forceinline__ float ln_P(const float h[8]) {
    float q0 = fmaf(h[1], h[1], h[0] * h[0]);
    float q1 = fmaf(h[3], h[3], h[2] * h[2]);
    float q2 = fmaf(h[5], h[5], h[4] * h[4]);
    float q3 = fmaf(h[7], h[7], h[6] * h[6]);
    float ss = (q0 + q1) + (q2 + q3);
    return rsqrtf(fmaf(ss, 0.125f, 1e-5f)) * KLOG2E;
}

// LN + tanh (uniform / general), in place. Zero-mean inputs.
__device__ __forceinline__ void ln_tanh_u(float h[8]) {
    float P = ln_P(h);
#pragma unroll
    for (int j = 0; j < 8; j++) h[j] = tanh_from_z2(h[j] * P);
}
__device__ __forceinline__ void ln_tanh_g(float h[8], const float* __restrict__ g,
                                          const float* __restrict__ kbe) {
    float P = ln_P(h);
#pragma unroll
    for (int j = 0; j < 8; j++)
        h[j] = tanh_from_z2(fmaf(h[j], P * g[j], kbe[j]));
}

// LN + rc only (layer 3: tanh folded into final dot). In place.
__device__ __forceinline__ void ln_rc_u(float h[8]) {
    float P = ln_P(h);
#pragma unroll
    for (int j = 0; j < 8; j++) h[j] = rc_from_z2(h[j] * P);
}
__device__ __forceinline__ void ln_rc_g(float h[8], const float* __restrict__ g,
                                        const float* __restrict__ kbe) {
    float P = ln_P(h);
#pragma unroll
    for (int j = 0; j < 8; j++)
        h[j] = rc_from_z2(fmaf(h[j], P * g[j], kbe[j]));
}

__device__ __forceinline__ void gemm8(const float hin[8], float hout[8],
                                      const float* __restrict__ W,
                                      const float* __restrict__ b) {
#pragma unroll
    for (int j = 0; j < 8; j++) {
        float a = b[j];
#pragma unroll
        for (int k = 0; k < 8; k++) a = fmaf(hin[k], W[k * 8 + j], a);
        hout[j] = a;
    }
}

__device__ __forceinline__ void load_idx(
    const int* __restrict__ ei, size_t E, int e0, int is64,
    int& s0, int& s1, int& d0, int& d1)
{
    if (is64) {
        int4 sw = *(const int4*)(ei + 2 * (size_t)e0);
        int4 dw = *(const int4*)(ei + 2 * (E + (size_t)e0));
        s0 = sw.x; s1 = sw.z; d0 = dw.x; d1 = dw.z;
    } else {
        int2 sw = *(const int2*)(ei + e0);
        int2 dw = *(const int2*)(ei + E + (size_t)e0);
        s0 = sw.x; s1 = sw.y; d0 = dw.x; d1 = dw.y;
    }
}

__global__ void __launch_bounds__(128, 5) edge_k(
    const int* __restrict__ ei, int E,
    const float* __restrict__ g1, const float* __restrict__ be1,
    const float* __restrict__ W2, const float* __restrict__ b2,
    const float* __restrict__ g2, const float* __restrict__ be2,
    const float* __restrict__ W3, const float* __restrict__ b3,
    const float* __restrict__ g3, const float* __restrict__ be3,
    const float* __restrict__ W4, const float* __restrict__ b4,
    float* __restrict__ out)
{
    __shared__ float sW2[64], sW3[64], sW4[8];
    __shared__ float sv[64];  // g1,kbe1,b2c,g2,kbe2,b3c,g3,kbe3
    __shared__ float sW4sum;  // b4 + sum(W4)
    __shared__ int sflag, suni;
    int t = threadIdx.x;
    if (t == 0) {
        sflag = detect_is64(ei);
        float ssum = b4[0];
#pragma unroll
        for (int j = 0; j < 8; j++) ssum += W4[j];
        sW4sum = ssum;
        int u = 1;
#pragma unroll
        for (int j = 0; j < 8; j++) {
            u &= (g1[j] == 1.0f) & (be1[j] == 0.0f);
            u &= (g2[j] == 1.0f) & (be2[j] == 0.0f);
            u &= (g3[j] == 1.0f) & (be3[j] == 0.0f);
        }
        suni = u;
    }
    // Channel-centered weights: each row's mean removed => linear-layer output
    // has exactly zero channel-mean for any input (LN is shift-invariant).
    if (t < 64) {
        int row = t >> 3;
        float m2 = 0.0f, m3 = 0.0f;
#pragma unroll
        for (int j = 0; j < 8; j++) { m2 += W2[row * 8 + j]; m3 += W3[row * 8 + j]; }
        sW2[t] = W2[t] - m2 * 0.125f;
        sW3[t] = W3[t] - m3 * 0.125f;
    }
    if (t < 8) {
        sW4[t] = W4[t];
        float mb2 = 0.0f, mb3 = 0.0f;
#pragma unroll
        for (int j = 0; j < 8; j++) { mb2 += b2[j]; mb3 += b3[j]; }
        sv[t]      = g1[t];  sv[8 + t]  = KLOG2E * be1[t];
        sv[16 + t] = b2[t] - mb2 * 0.125f;
        sv[24 + t] = g2[t];  sv[32 + t] = KLOG2E * be2[t];
        sv[40 + t] = b3[t] - mb3 * 0.125f;
        sv[48 + t] = g3[t];  sv[56 + t] = KLOG2E * be3[t];
    }
    __syncthreads();

    const float* sg1 = sv;       const float* skb1 = sv + 8;
    const float* sb2 = sv + 16;  const float* sg2  = sv + 24; const float* skb2 = sv + 32;
    const float* sb3 = sv + 40;  const float* sg3  = sv + 48; const float* skb3 = sv + 56;

    const int is64 = sflag;
    const int uni  = suni;
    const float w4sum = sW4sum;
    const int stride2 = gridDim.x * blockDim.x * 2;
    int e0 = (blockIdx.x * blockDim.x + t) * 2;

    int s0 = 0, s1 = 0, d0 = 0, d1 = 0;
    bool pv = (e0 + 1 < E);
    if (pv) load_idx(ei, (size_t)E, e0, is64, s0, s1, d0, d1);

    while (e0 < E) {
        int e1 = e0 + stride2;
        if (pv) {
            int ns0 = 0, ns1 = 0, nd0 = 0, nd1 = 0;
            bool npv = (e1 + 1 < E);
            if (npv) load_idx(ei, (size_t)E, e1, is64, ns0, ns1, nd0, nd1);

            const float4* apA = (const float4*)(g_xs + (size_t)s0 * 8);
            const float4* bpA = (const float4*)(g_xb + (size_t)d0 * 8);
            const float4* apB = (const float4*)(g_xs + (size_t)s1 * 8);
            const float4* bpB = (const float4*)(g_xb + (size_t)d1 * 8);
            float4 a0A = apA[0], a1A = apA[1], c0A = bpA[0], c1A = bpA[1];
            float4 a0B = apB[0], a1B = apB[1], c0B = bpB[0], c1B = bpB[1];

            float hA[8] = { a0A.x + c0A.x, a0A.y + c0A.y, a0A.z + c0A.z, a0A.w + c0A.w,
                            a1A.x + c1A.x, a1A.y + c1A.y, a1A.z + c1A.z, a1A.w + c1A.w };
            float hB[8] = { a0B.x + c0B.x, a0B.y + c0B.y, a0B.z + c0B.z, a0B.w + c0B.w,
                            a1B.x + c1B.x, a1B.y + c1B.y, a1B.z + c1B.z, a1B.w + c1B.w };

            float h2A[8], h2B[8], h3A[8], h3B[8];
            if (uni) {
                ln_tanh_u(hA);                    ln_tanh_u(hB);
                gemm8(hA, h2A, sW2, sb2);         gemm8(hB, h2B, sW2, sb2);
                ln_tanh_u(h2A);                   ln_tanh_u(h2B);
                gemm8(h2A, h3A, sW3, sb3);        gemm8(h2B, h3B, sW3, sb3);
                ln_rc_u(h3A);                     ln_rc_u(h3B);
            } else {
                ln_tanh_g(hA, sg1, skb1);         ln_tanh_g(hB, sg1, skb1);
                gemm8(hA, h2A, sW2, sb2);         gemm8(hB, h2B, sW2, sb2);
                ln_tanh_g(h2A, sg2, skb2);        ln_tanh_g(h2B, sg2, skb2);
                gemm8(h2A, h3A, sW3, sb3);        gemm8(h2B, h3B, sW3, sb3);
                ln_rc_g(h3A, sg3, skb3);          ln_rc_g(h3B, sg3, skb3);
            }

            // out = (b4 + sum(W4)) - 2 * sum_j rc_j * W4_j
            float dA = 0.0f, dB = 0.0f;
#pragma unroll
            for (int k = 0; k < 8; k++) {
                float w = sW4[k];
                dA = fmaf(h3A[k], w, dA);
                dB = fmaf(h3B[k], w, dB);
            }
            float oA = fmaf(-2.0f, dA, w4sum);
            float oB = fmaf(-2.0f, dB, w4sum);
            *(float2*)(out + e0) = make_float2(oA, oB);

            s0 = ns0; s1 = ns1; d0 = nd0; d1 = nd1;
            pv = npv;
        } else {
            // scalar tail (e0 == E-1, only when E is odd)
            int s, d;
            if (is64) { s = ei[2 * (size_t)e0]; d = ei[2 * ((size_t)E + e0)]; }
            else      { s = ei[e0];             d = ei[(size_t)E + e0]; }
            const float4* ap = (const float4*)(g_xs + (size_t)s * 8);
            const float4* bp = (const float4*)(g_xb + (size_t)d * 8);
            float4 a0 = ap[0], a1 = ap[1], c0 = bp[0], c1 = bp[1];
            float h[8] = { a0.x + c0.x, a0.y + c0.y, a0.z + c0.z, a0.w + c0.w,
                           a1.x + c1.x, a1.y + c1.y, a1.z + c1.z, a1.w + c1.w };
            float h2[8], h3[8];
            if (uni) {
                ln_tanh_u(h);
                gemm8(h, h2, sW2, sb2);
                ln_tanh_u(h2);
                gemm8(h2, h3, sW3, sb3);
                ln_rc_u(h3);
            } else {
                ln_tanh_g(h, sg1, skb1);
                gemm8(h, h2, sW2, sb2);
                ln_tanh_g(h2, sg2, skb2);
                gemm8(h2, h3, sW3, sb3);
                ln_rc_g(h3, sg3, skb3);
            }
            float dd = 0.0f;
#pragma unroll
            for (int k = 0; k < 8; k++) dd = fmaf(h3[k], sW4[k], dd);
            out[e0] = fmaf(-2.0f, dd, w4sum);
            pv = (e1 + 1 < E);
            if (pv) load_idx(ei, (size_t)E, e1, is64, s0, s1, d0, d1);
        }
        e0 = e1;
    }
}

// ---------------------------------------------------------------------------
extern "C" void kernel_launch(void* const* d_in, const int* in_sizes, int n_in,
                              void* d_out, int out_size)
{
    const float* x     = (const float*)d_in[0];
    const int*   ei    = (const int*)d_in[1];
    const float* vp    = (const float*)d_in[2];
    const int*   batch = (const int*)d_in[3];
    const float* W1  = (const float*)d_in[4];
    const float* b1  = (const float*)d_in[5];
    const float* g1  = (const float*)d_in[6];
    const float* be1 = (const float*)d_in[7];
    const float* W2  = (const float*)d_in[8];
    const float* b2  = (const float*)d_in[9];
    const float* g2  = (const float*)d_in[10];
    const float* be2 = (const float*)d_in[11];
    const float* W3  = (const float*)d_in[12];
    const float* b3  = (const float*)d_in[13];
    const float* g3  = (const float*)d_in[14];
    const float* be3 = (const float*)d_in[15];
    const float* W4  = (const float*)d_in[16];
    const float* b4  = (const float*)d_in[17];

    int N = in_sizes[0] / 16;
    int E = in_sizes[1] / 2;
    int G = in_sizes[2] / 16;

    int pb = (N + 255) / 256;
    pre_k<<<pb, 256>>>(x, batch, vp, W1, b1, ei, N, G);

    // persistent 1-wave grid: 5 blocks/SM x 148 SMs = 20 warps/SM
    int eb = 740;
    long long need = ((long long)E / 2 + 127) / 128;
    if (need < eb) eb = (int)(need > 0 ? need : 1);
    edge_k<<<eb, 128>>>(ei, E, g1, be1, W2, b2, g2, be2, W3, b3, g3, be3,
                        W4, b4, (float*)d_out);
}

// round 15
// speedup vs baseline: 1.2406x; 1.0235x over previous
#include <cuda_runtime.h>

// ---------------------------------------------------------------------------
// EdgeNetwork: per-node factorization + 2 edges/thread (scalar math).
//   pre_k : xs[n] = center(x@W1a + b1 + vp[batch]@W1c); xb[n] = center(x@W1b)
//   edge_k: mean-free LN (centered weights), K-folded tanh, layer-3 rc-fold,
//           persistent grid. R15: TWO-LEVEL software pipeline -- iteration i
//           issues the record gathers for i+1 (indices prefetched at i-1),
//           so compute never waits on L2 gather latency.
// ---------------------------------------------------------------------------

#define NODE_CAP 131072
#define KLOG2E 2.8853900817779268f   // 2*log2(e)

__device__ __align__(16) float g_xs[NODE_CAP * 8];
__device__ __align__(16) float g_xb[NODE_CAP * 8];

__device__ __forceinline__ int detect_is64(const int* __restrict__ ei) {
    int nz = 0;
#pragma unroll
    for (int i = 1; i < 16; i += 2) nz |= ei[i];
    return nz == 0;
}

// ---------------------------------------------------------------------------
// Per-node precompute; xs/xb stored mean-centered (LN is shift-invariant).
// ---------------------------------------------------------------------------
__global__ void __launch_bounds__(256) pre_k(
    const float* __restrict__ x, const int* __restrict__ batch_raw,
    const float* __restrict__ vp, const float* __restrict__ W1,
    const float* __restrict__ b1, const int* __restrict__ ei, int N, int G)
{
    __shared__ float sW1[48 * 8];
    __shared__ float svp[64 * 16];
    __shared__ float sb1[8];
    __shared__ int sflag;
    int t = threadIdx.x;
    if (t == 0) sflag = detect_is64(ei);
    for (int i = t; i < 384; i += blockDim.x) sW1[i] = W1[i];
    int gv = G * 16; if (gv > 1024) gv = 1024;
    for (int i = t; i < gv; i += blockDim.x) svp[i] = vp[i];
    if (t < 8) sb1[t] = b1[t];
    __syncthreads();

    int n = blockIdx.x * blockDim.x + t;
    if (n >= N) return;

    int g = sflag ? batch_raw[2 * n] : batch_raw[n];

    float xi[16];
    const float* xr = x + (size_t)n * 16;
#pragma unroll
    for (int k = 0; k < 16; k += 4) {
        float4 v = *(const float4*)(xr + k);
        xi[k] = v.x; xi[k + 1] = v.y; xi[k + 2] = v.z; xi[k + 3] = v.w;
    }
    const float* vg = svp + g * 16;

    float xs[8], xb[8];
#pragma unroll
    for (int j = 0; j < 8; j++) {
        float a = sb1[j];
        float b = 0.0f;
#pragma unroll
        for (int k = 0; k < 16; k++) {
            a = fmaf(xi[k], sW1[k * 8 + j], a);
            a = fmaf(vg[k], sW1[(32 + k) * 8 + j], a);
            b = fmaf(xi[k], sW1[(16 + k) * 8 + j], b);
        }
        xs[j] = a; xb[j] = b;
    }
    float ms = 0.0f, mb = 0.0f;
#pragma unroll
    for (int j = 0; j < 8; j++) { ms += xs[j]; mb += xb[j]; }
    ms *= 0.125f; mb *= 0.125f;
#pragma unroll
    for (int j = 0; j < 8; j++) { xs[j] -= ms; xb[j] -= mb; }

    float4* o1 = (float4*)(g_xs + (size_t)n * 8);
    o1[0] = make_float4(xs[0], xs[1], xs[2], xs[3]);
    o1[1] = make_float4(xs[4], xs[5], xs[6], xs[7]);
    float4* o2 = (float4*)(g_xb + (size_t)n * 8);
    o2[0] = make_float4(xb[0], xb[1], xb[2], xb[3]);
    o2[1] = make_float4(xb[4], xb[5], xb[6], xb[7]);
}

// ---------------------------------------------------------------------------
// tanh pieces: z2 = 2*log2(e)*z ; rc = rcp(ex2(z2)+1) ; tanh = 1 - 2*rc
// ---------------------------------------------------------------------------
__device__ __forceinline__ float rc_from_z2(float z2) {
    float q, rc;
    asm("ex2.approx.f32 %0, %1;" : "=f"(q) : "f"(z2));
    float sum = q + 1.0f;
    asm("rcp.approx.f32 %0, %1;" : "=f"(rc) : "f"(sum));
    return rc;
}
__device__ __forceinline__ float tanh_from_z2(float z2) {
    return fmaf(-2.0f, rc_from_z2(z2), 1.0f);
}

// Mean-free LN scale (zero channel-mean inputs by construction).
__device__ __forceinline__ float ln_P(const float h[8]) {
    float q0 = fmaf(h[1], h[1], h[0] * h[0]);
    float q1 = fmaf(h[3], h[3], h[2] * h[2]);
    float q2 = fmaf(h[5], h[5], h[4] * h[4]);
    float q3 = fmaf(h[7], h[7], h[6] * h[6]);
    float ss = (q0 + q1) + (q2 + q3);
    return rsqrtf(fmaf(ss, 0.125f, 1e-5f)) * KLOG2E;
}

__device__ __forceinline__ void ln_tanh_u(float h[8]) {
    float P = ln_P(h);
#pragma unroll
    for (int j = 0; j < 8; j++) h[j] = tanh_from_z2(h[j] * P);
}
__device__ __forceinline__ void ln_tanh_g(float h[8], const float* __restrict__ g,
                                          const float* __restrict__ kbe) {
    float P = ln_P(h);
#pragma unroll
    for (int j = 0; j < 8; j++)
        h[j] = tanh_from_z2(fmaf(h[j], P * g[j], kbe[j]));
}
__device__ __forceinline__ void ln_rc_u(float h[8]) {
    float P = ln_P(h);
#pragma unroll
    for (int j = 0; j < 8; j++) h[j] = rc_from_z2(h[j] * P);
}
__device__ __forceinline__ void ln_rc_g(float h[8], const float* __restrict__ g,
                                        const float* __restrict__ kbe) {
    float P = ln_P(h);
#pragma unroll
    for (int j = 0; j < 8; j++)
        h[j] = rc_from_z2(fmaf(h[j], P * g[j], kbe[j]));
}

__device__ __forceinline__ void gemm8(const float hin[8], float hout[8],
                                      const float* __restrict__ W,
                                      const float* __restrict__ b) {
#pragma unroll
    for (int j = 0; j < 8; j++) {
        float a = b[j];
#pragma unroll
        for (int k = 0; k < 8; k++) a = fmaf(hin[k], W[k * 8 + j], a);
        hout[j] = a;
    }
}

__device__ __forceinline__ void load_idx(
    const int* __restrict__ ei, size_t E, int e0, int is64,
    int& s0, int& s1, int& d0, int& d1)
{
    if (is64) {
        int4 sw = *(const int4*)(ei + 2 * (size_t)e0);
        int4 dw = *(const int4*)(ei + 2 * (E + (size_t)e0));
        s0 = sw.x; s1 = sw.z; d0 = dw.x; d1 = dw.z;
    } else {
        int2 sw = *(const int2*)(ei + e0);
        int2 dw = *(const int2*)(ei + E + (size_t)e0);
        s0 = sw.x; s1 = sw.y; d0 = dw.x; d1 = dw.y;
    }
}

__device__ __forceinline__ void load_recs(
    int s0, int d0, int s1, int d1,
    float4& As0, float4& As1, float4& Ab0, float4& Ab1,
    float4& Bs0, float4& Bs1, float4& Bb0, float4& Bb1)
{
    const float4* p;
    p = (const float4*)(g_xs + (size_t)s0 * 8); As0 = p[0]; As1 = p[1];
    p = (const float4*)(g_xb + (size_t)d0 * 8); Ab0 = p[0]; Ab1 = p[1];
    p = (const float4*)(g_xs + (size_t)s1 * 8); Bs0 = p[0]; Bs1 = p[1];
    p = (const float4*)(g_xb + (size_t)d1 * 8); Bb0 = p[0]; Bb1 = p[1];
}

__global__ void __launch_bounds__(128, 4) edge_k(
    const int* __restrict__ ei, int E,
    const float* __restrict__ g1, const float* __restrict__ be1,
    const float* __restrict__ W2, const float* __restrict__ b2,
    const float* __restrict__ g2, const float* __restrict__ be2,
    const float* __restrict__ W3, const float* __restrict__ b3,
    const float* __restrict__ g3, const float* __restrict__ be3,
    const float* __restrict__ W4, const float* __restrict__ b4,
    float* __restrict__ out)
{
    __shared__ float sW2[64], sW3[64], sW4[8];
    __shared__ float sv[64];
    __shared__ float sW4sum;
    __shared__ int sflag, suni;
    int t = threadIdx.x;
    if (t == 0) {
        sflag = detect_is64(ei);
        float ssum = b4[0];
#pragma unroll
        for (int j = 0; j < 8; j++) ssum += W4[j];
        sW4sum = ssum;
        int u = 1;
#pragma unroll
        for (int j = 0; j < 8; j++) {
            u &= (g1[j] == 1.0f) & (be1[j] == 0.0f);
            u &= (g2[j] == 1.0f) & (be2[j] == 0.0f);
            u &= (g3[j] == 1.0f) & (be3[j] == 0.0f);
        }
        suni = u;
    }
    // Channel-centered weights (mean-free LN).
    if (t < 64) {
        int row = t >> 3;
        float m2 = 0.0f, m3 = 0.0f;
#pragma unroll
        for (int j = 0; j < 8; j++) { m2 += W2[row * 8 + j]; m3 += W3[row * 8 + j]; }
        sW2[t] = W2[t] - m2 * 0.125f;
        sW3[t] = W3[t] - m3 * 0.125f;
    }
    if (t < 8) {
        sW4[t] = W4[t];
        float mb2 = 0.0f, mb3 = 0.0f;
#pragma unroll
        for (int j = 0; j < 8; j++) { mb2 += b2[j]; mb3 += b3[j]; }
        sv[t]      = g1[t];  sv[8 + t]  = KLOG2E * be1[t];
        sv[16 + t] = b2[t] - mb2 * 0.125f;
        sv[24 + t] = g2[t];  sv[32 + t] = KLOG2E * be2[t];
        sv[40 + t] = b3[t] - mb3 * 0.125f;
        sv[48 + t] = g3[t];  sv[56 + t] = KLOG2E * be3[t];
    }
    __syncthreads();

    const float* sg1 = sv;       const float* skb1 = sv + 8;
    const float* sb2 = sv + 16;  const float* sg2  = sv + 24; const float* skb2 = sv + 32;
    const float* sb3 = sv + 40;  const float* sg3  = sv + 48; const float* skb3 = sv + 56;

    const int is64 = sflag;
    const int uni  = suni;
    const float w4sum = sW4sum;
    const int stride2 = gridDim.x * blockDim.x * 2;
    const int eSafe = (E >= 2) ? (E - 2) : 0;   // clamp so pair loads stay in-bounds

    int e = (blockIdx.x * blockDim.x + t) * 2;

    // ---- pipeline prologue ----
    float4 As0, As1, Ab0, Ab1, Bs0, Bs1, Bb0, Bb1;   // current records
    int ns0 = 0, ns1 = 0, nd0 = 0, nd1 = 0;          // indices for NEXT iter
    if (e < E) {
        int s0, s1, d0, d1;
        int ec = e <= eSafe ? e : eSafe;
        load_idx(ei, (size_t)E, ec, is64, s0, s1, d0, d1);
        load_recs(s0, d0, s1, d1, As0, As1, Ab0, Ab1, Bs0, Bs1, Bb0, Bb1);
        int en = e + stride2;
        if (en < E) {
            int enc = en <= eSafe ? en : eSafe;
            load_idx(ei, (size_t)E, enc, is64, ns0, ns1, nd0, nd1);
        }
    }

    while (e < E) {
        int en = e + stride2;
        bool nv = (en < E);

        // 1) issue NEXT iteration's record gathers (indices already resident)
        float4 pAs0, pAs1, pAb0, pAb1, pBs0, pBs1, pBb0, pBb1;
        if (nv)
            load_recs(ns0, nd0, ns1, nd1,
                      pAs0, pAs1, pAb0, pAb1, pBs0, pBs1, pBb0, pBb1);

        // 2) prefetch indices two iterations ahead
        int ms0 = 0, ms1 = 0, md0 = 0, md1 = 0;
        int en2 = en + stride2;
        if (en2 < E) {
            int ec2 = en2 <= eSafe ? en2 : eSafe;
            load_idx(ei, (size_t)E, ec2, is64, ms0, ms1, md0, md1);
        }

        // 3) compute on CURRENT records (already in registers)
        float hA[8] = { As0.x + Ab0.x, As0.y + Ab0.y, As0.z + Ab0.z, As0.w + Ab0.w,
                        As1.x + Ab1.x, As1.y + Ab1.y, As1.z + Ab1.z, As1.w + Ab1.w };
        float hB[8] = { Bs0.x + Bb0.x, Bs0.y + Bb0.y, Bs0.z + Bb0.z, Bs0.w + Bb0.w,
                        Bs1.x + Bb1.x, Bs1.y + Bb1.y, Bs1.z + Bb1.z, Bs1.w + Bb1.w };

        float h2A[8], h2B[8], h3A[8], h3B[8];
        if (uni) {
            ln_tanh_u(hA);                    ln_tanh_u(hB);
            gemm8(hA, h2A, sW2, sb2);         gemm8(hB, h2B, sW2, sb2);
            ln_tanh_u(h2A);                   ln_tanh_u(h2B);
            gemm8(h2A, h3A, sW3, sb3);        gemm8(h2B, h3B, sW3, sb3);
            ln_rc_u(h3A);                     ln_rc_u(h3B);
        } else {
            ln_tanh_g(hA, sg1, skb1);         ln_tanh_g(hB, sg1, skb1);
            gemm8(hA, h2A, sW2, sb2);         gemm8(hB, h2B, sW2, sb2);
            ln_tanh_g(h2A, sg2, skb2);        ln_tanh_g(h2B, sg2, skb2);
            gemm8(h2A, h3A, sW3, sb3);        gemm8(h2B, h3B, sW3, sb3);
            ln_rc_g(h3A, sg3, skb3);          ln_rc_g(h3B, sg3, skb3);
        }

        float dA = 0.0f, dB = 0.0f;
#pragma unroll
        for (int k = 0; k < 8; k++) {
            float w = sW4[k];
            dA = fmaf(h3A[k], w, dA);
            dB = fmaf(h3B[k], w, dB);
        }
        float oA = fmaf(-2.0f, dA, w4sum);
        float oB = fmaf(-2.0f, dB, w4sum);
        if (e + 1 < E) *(float2*)(out + e) = make_float2(oA, oB);
        else           out[e] = oA;

        // 4) rotate pipeline state
        if (!nv) break;
        As0 = pAs0; As1 = pAs1; Ab0 = pAb0; Ab1 = pAb1;
        Bs0 = pBs0; Bs1 = pBs1; Bb0 = pBb0; Bb1 = pBb1;
        ns0 = ms0; ns1 = ms1; nd0 = md0; nd1 = md1;
        e = en;
    }
}

// ---------------------------------------------------------------------------
extern "C" void kernel_launch(void* const* d_in, const int* in_sizes, int n_in,
                              void* d_out, int out_size)
{
    const float* x     = (const float*)d_in[0];
    const int*   ei    = (const int*)d_in[1];
    const float* vp    = (const float*)d_in[2];
    const int*   batch = (const int*)d_in[3];
    const float* W1  = (const float*)d_in[4];
    const float* b1  = (const float*)d_in[5];
    const float* g1  = (const float*)d_in[6];
    const float* be1 = (const float*)d_in[7];
    const float* W2  = (const float*)d_in[8];
    const float* b2  = (const float*)d_in[9];
    const float* g2  = (const float*)d_in[10];
    const float* be2 = (const float*)d_in[11];
    const float* W3  = (const float*)d_in[12];
    const float* b3  = (const float*)d_in[13];
    const float* g3  = (const float*)d_in[14];
    const float* be3 = (const float*)d_in[15];
    const float* W4  = (const float*)d_in[16];
    const float* b4  = (const float*)d_in[17];

    int N = in_sizes[0] / 16;
    int E = in_sizes[1] / 2;
    int G = in_sizes[2] / 16;

    int pb = (N + 255) / 256;
    pre_k<<<pb, 256>>>(x, batch, vp, W1, b1, ei, N, G);

    // persistent 1-wave grid: 4 blocks/SM x 148 SMs = 16 warps/SM
    int eb = 592;
    long long need = ((long long)E / 2 + 127) / 128;
    if (need < eb) eb = (int)(need > 0 ? need : 1);
    edge_k<<<eb, 128>>>(ei, E, g1, be1, W2, b2, g2, be2, W3, b3, g3, be3,
                        W4, b4, (float*)d_out);
}

// round 16
// speedup vs baseline: 1.2482x; 1.0061x over previous
#include <cuda_runtime.h>

// ---------------------------------------------------------------------------
// EdgeNetwork: per-node factorization + 2 edges/thread (scalar math).
//   pre_k : xs[n] = center(x@W1a + b1 + vp[batch]@W1c); xb[n] = center(x@W1b)
//   edge_k: mean-free LN (centered weights), K-folded tanh, layer-3 rc-fold,
//           2-level software pipeline, persistent grid.
//   R16: 256-bit gathers (ld.global.nc.v8.f32, sm_100+) -- one instruction
//        per 32B node record: L1 wavefronts and LDG issue count halved.
// ---------------------------------------------------------------------------

#define NODE_CAP 131072
#define KLOG2E 2.8853900817779268f   // 2*log2(e)

__device__ __align__(32) float g_xs[NODE_CAP * 8];
__device__ __align__(32) float g_xb[NODE_CAP * 8];

__device__ __forceinline__ int detect_is64(const int* __restrict__ ei) {
    int nz = 0;
#pragma unroll
    for (int i = 1; i < 16; i += 2) nz |= ei[i];
    return nz == 0;
}

// 256-bit read-only global load (sm_100+): full 32B record in one LDG.
__device__ __forceinline__ void ldg256(const float* __restrict__ p,
                                       float4& a, float4& b) {
    asm("ld.global.nc.v8.f32 {%0,%1,%2,%3,%4,%5,%6,%7}, [%8];"
        : "=f"(a.x), "=f"(a.y), "=f"(a.z), "=f"(a.w),
          "=f"(b.x), "=f"(b.y), "=f"(b.z), "=f"(b.w)
        : "l"(p));
}

// ---------------------------------------------------------------------------
// Per-node precompute; xs/xb stored mean-centered (LN is shift-invariant).
// ---------------------------------------------------------------------------
__global__ void __launch_bounds__(256) pre_k(
    const float* __restrict__ x, const int* __restrict__ batch_raw,
    const float* __restrict__ vp, const float* __restrict__ W1,
    const float* __restrict__ b1, const int* __restrict__ ei, int N, int G)
{
    __shared__ float sW1[48 * 8];
    __shared__ float svp[64 * 16];
    __shared__ float sb1[8];
    __shared__ int sflag;
    int t = threadIdx.x;
    if (t == 0) sflag = detect_is64(ei);
    for (int i = t; i < 384; i += blockDim.x) sW1[i] = W1[i];
    int gv = G * 16; if (gv > 1024) gv = 1024;
    for (int i = t; i < gv; i += blockDim.x) svp[i] = vp[i];
    if (t < 8) sb1[t] = b1[t];
    __syncthreads();

    int n = blockIdx.x * blockDim.x + t;
    if (n >= N) return;

    int g = sflag ? batch_raw[2 * n] : batch_raw[n];

    float xi[16];
    const float* xr = x + (size_t)n * 16;
#pragma unroll
    for (int k = 0; k < 16; k += 4) {
        float4 v = *(const float4*)(xr + k);
        xi[k] = v.x; xi[k + 1] = v.y; xi[k + 2] = v.z; xi[k + 3] = v.w;
    }
    const float* vg = svp + g * 16;

    float xs[8], xb[8];
#pragma unroll
    for (int j = 0; j < 8; j++) {
        float a = sb1[j];
        float b = 0.0f;
#pragma unroll
        for (int k = 0; k < 16; k++) {
            a = fmaf(xi[k], sW1[k * 8 + j], a);
            a = fmaf(vg[k], sW1[(32 + k) * 8 + j], a);
            b = fmaf(xi[k], sW1[(16 + k) * 8 + j], b);
        }
        xs[j] = a; xb[j] = b;
    }
    float ms = 0.0f, mb = 0.0f;
#pragma unroll
    for (int j = 0; j < 8; j++) { ms += xs[j]; mb += xb[j]; }
    ms *= 0.125f; mb *= 0.125f;
#pragma unroll
    for (int j = 0; j < 8; j++) { xs[j] -= ms; xb[j] -= mb; }

    float4* o1 = (float4*)(g_xs + (size_t)n * 8);
    o1[0] = make_float4(xs[0], xs[1], xs[2], xs[3]);
    o1[1] = make_float4(xs[4], xs[5], xs[6], xs[7]);
    float4* o2 = (float4*)(g_xb + (size_t)n * 8);
    o2[0] = make_float4(xb[0], xb[1], xb[2], xb[3]);
    o2[1] = make_float4(xb[4], xb[5], xb[6], xb[7]);
}

// ---------------------------------------------------------------------------
// tanh pieces: z2 = 2*log2(e)*z ; rc = rcp(ex2(z2)+1) ; tanh = 1 - 2*rc
// ---------------------------------------------------------------------------
__device__ __forceinline__ float rc_from_z2(float z2) {
    float q, rc;
    asm("ex2.approx.f32 %0, %1;" : "=f"(q) : "f"(z2));
    float sum = q + 1.0f;
    asm("rcp.approx.f32 %0, %1;" : "=f"(rc) : "f"(sum));
    return rc;
}
__device__ __forceinline__ float tanh_from_z2(float z2) {
    return fmaf(-2.0f, rc_from_z2(z2), 1.0f);
}

// Mean-free LN scale (zero channel-mean inputs by construction).
__device__ __forceinline__ float ln_P(const float h[8]) {
    float q0 = fmaf(h[1], h[1], h[0] * h[0]);
    float q1 = fmaf(h[3], h[3], h[2] * h[2]);
    float q2 = fmaf(h[5], h[5], h[4] * h[4]);
    float q3 = fmaf(h[7], h[7], h[6] * h[6]);
    float ss = (q0 + q1) + (q2 + q3);
    return rsqrtf(fmaf(ss, 0.125f, 1e-5f)) * KLOG2E;
}

__device__ __forceinline__ void ln_tanh_u(float h[8]) {
    float P = ln_P(h);
#pragma unroll
    for (int j = 0; j < 8; j++) h[j] = tanh_from_z2(h[j] * P);
}
__device__ __forceinline__ void ln_tanh_g(float h[8], const float* __restrict__ g,
                                          const float* __restrict__ kbe) {
    float P = ln_P(h);
#pragma unroll
    for (int j = 0; j < 8; j++)
        h[j] = tanh_from_z2(fmaf(h[j], P * g[j], kbe[j]));
}
__device__ __forceinline__ void ln_rc_u(float h[8]) {
    float P = ln_P(h);
#pragma unroll
    for (int j = 0; j < 8; j++) h[j] = rc_from_z2(h[j] * P);
}
__device__ __forceinline__ void ln_rc_g(float h[8], const float* __restrict__ g,
                                        const float* __restrict__ kbe) {
    float P = ln_P(h);
#pragma unroll
    for (int j = 0; j < 8; j++)
        h[j] = rc_from_z2(fmaf(h[j], P * g[j], kbe[j]));
}

__device__ __forceinline__ void gemm8(const float hin[8], float hout[8],
                                      const float* __restrict__ W,
                                      const float* __restrict__ b) {
#pragma unroll
    for (int j = 0; j < 8; j++) {
        float a = b[j];
#pragma unroll
        for (int k = 0; k < 8; k++) a = fmaf(hin[k], W[k * 8 + j], a);
        hout[j] = a;
    }
}

__device__ __forceinline__ void load_idx(
    const int* __restrict__ ei, size_t E, int e0, int is64,
    int& s0, int& s1, int& d0, int& d1)
{
    if (is64) {
        int4 sw = *(const int4*)(ei + 2 * (size_t)e0);
        int4 dw = *(const int4*)(ei + 2 * (E + (size_t)e0));
        s0 = sw.x; s1 = sw.z; d0 = dw.x; d1 = dw.z;
    } else {
        int2 sw = *(const int2*)(ei + e0);
        int2 dw = *(const int2*)(ei + E + (size_t)e0);
        s0 = sw.x; s1 = sw.y; d0 = dw.x; d1 = dw.y;
    }
}

// Gather 4 node records with 256-bit loads (one LDG.256 per record).
__device__ __forceinline__ void load_recs(
    int s0, int d0, int s1, int d1,
    float4& As0, float4& As1, float4& Ab0, float4& Ab1,
    float4& Bs0, float4& Bs1, float4& Bb0, float4& Bb1)
{
    ldg256(g_xs + (size_t)s0 * 8, As0, As1);
    ldg256(g_xb + (size_t)d0 * 8, Ab0, Ab1);
    ldg256(g_xs + (size_t)s1 * 8, Bs0, Bs1);
    ldg256(g_xb + (size_t)d1 * 8, Bb0, Bb1);
}

__global__ void __launch_bounds__(128, 4) edge_k(
    const int* __restrict__ ei, int E,
    const float* __restrict__ g1, const float* __restrict__ be1,
    const float* __restrict__ W2, const float* __restrict__ b2,
    const float* __restrict__ g2, const float* __restrict__ be2,
    const float* __restrict__ W3, const float* __restrict__ b3,
    const float* __restrict__ g3, const float* __restrict__ be3,
    const float* __restrict__ W4, const float* __restrict__ b4,
    float* __restrict__ out)
{
    __shared__ float sW2[64], sW3[64], sW4[8];
    __shared__ float sv[64];
    __shared__ float sW4sum;
    __shared__ int sflag, suni;
    int t = threadIdx.x;
    if (t == 0) {
        sflag = detect_is64(ei);
        float ssum = b4[0];
#pragma unroll
        for (int j = 0; j < 8; j++) ssum += W4[j];
        sW4sum = ssum;
        int u = 1;
#pragma unroll
        for (int j = 0; j < 8; j++) {
            u &= (g1[j] == 1.0f) & (be1[j] == 0.0f);
            u &= (g2[j] == 1.0f) & (be2[j] == 0.0f);
            u &= (g3[j] == 1.0f) & (be3[j] == 0.0f);
        }
        suni = u;
    }
    // Channel-centered weights (mean-free LN).
    if (t < 64) {
        int row = t >> 3;
        float m2 = 0.0f, m3 = 0.0f;
#pragma unroll
        for (int j = 0; j < 8; j++) { m2 += W2[row * 8 + j]; m3 += W3[row * 8 + j]; }
        sW2[t] = W2[t] - m2 * 0.125f;
        sW3[t] = W3[t] - m3 * 0.125f;
    }
    if (t < 8) {
        sW4[t] = W4[t];
        float mb2 = 0.0f, mb3 = 0.0f;
#pragma unroll
        for (int j = 0; j < 8; j++) { mb2 += b2[j]; mb3 += b3[j]; }
        sv[t]      = g1[t];  sv[8 + t]  = KLOG2E * be1[t];
        sv[16 + t] = b2[t] - mb2 * 0.125f;
        sv[24 + t] = g2[t];  sv[32 + t] = KLOG2E * be2[t];
        sv[40 + t] = b3[t] - mb3 * 0.125f;
        sv[48 + t] = g3[t];  sv[56 + t] = KLOG2E * be3[t];
    }
    __syncthreads();

    const float* sg1 = sv;       const float* skb1 = sv + 8;
    const float* sb2 = sv + 16;  const float* sg2  = sv + 24; const float* skb2 = sv + 32;
    const float* sb3 = sv + 40;  const float* sg3  = sv + 48; const float* skb3 = sv + 56;

    const int is64 = sflag;
    const int uni  = suni;
    const float w4sum = sW4sum;
    const int stride2 = gridDim.x * blockDim.x * 2;
    const int eSafe = (E >= 2) ? (E - 2) : 0;   // clamp so pair loads stay in-bounds

    int e = (blockIdx.x * blockDim.x + t) * 2;

    // ---- pipeline prologue ----
    float4 As0, As1, Ab0, Ab1, Bs0, Bs1, Bb0, Bb1;   // current records
    int ns0 = 0, ns1 = 0, nd0 = 0, nd1 = 0;          // indices for NEXT iter
    if (e < E) {
        int s0, s1, d0, d1;
        int ec = e <= eSafe ? e : eSafe;
        load_idx(ei, (size_t)E, ec, is64, s0, s1, d0, d1);
        load_recs(s0, d0, s1, d1, As0, As1, Ab0, Ab1, Bs0, Bs1, Bb0, Bb1);
        int en = e + stride2;
        if (en < E) {
            int enc = en <= eSafe ? en : eSafe;
            load_idx(ei, (size_t)E, enc, is64, ns0, ns1, nd0, nd1);
        }
    }

    while (e < E) {
        int en = e + stride2;
        bool nv = (en < E);

        // 1) issue NEXT iteration's record gathers (indices already resident)
        float4 pAs0, pAs1, pAb0, pAb1, pBs0, pBs1, pBb0, pBb1;
        if (nv)
            load_recs(ns0, nd0, ns1, nd1,
                      pAs0, pAs1, pAb0, pAb1, pBs0, pBs1, pBb0, pBb1);

        // 2) prefetch indices two iterations ahead
        int ms0 = 0, ms1 = 0, md0 = 0, md1 = 0;
        int en2 = en + stride2;
        if (en2 < E) {
            int ec2 = en2 <= eSafe ? en2 : eSafe;
            load_idx(ei, (size_t)E, ec2, is64, ms0, ms1, md0, md1);
        }

        // 3) compute on CURRENT records (already in registers)
        float hA[8] = { As0.x + Ab0.x, As0.y + Ab0.y, As0.z + Ab0.z, As0.w + Ab0.w,
                        As1.x + Ab1.x, As1.y + Ab1.y, As1.z + Ab1.z, As1.w + Ab1.w };
        float hB[8] = { Bs0.x + Bb0.x, Bs0.y + Bb0.y, Bs0.z + Bb0.z, Bs0.w + Bb0.w,
                        Bs1.x + Bb1.x, Bs1.y + Bb1.y, Bs1.z + Bb1.z, Bs1.w + Bb1.w };

        float h2A[8], h2B[8], h3A[8], h3B[8];
        if (uni) {
            ln_tanh_u(hA);                    ln_tanh_u(hB);
            gemm8(hA, h2A, sW2, sb2);         gemm8(hB, h2B, sW2, sb2);
            ln_tanh_u(h2A);                   ln_tanh_u(h2B);
            gemm8(h2A, h3A, sW3, sb3);        gemm8(h2B, h3B, sW3, sb3);
            ln_rc_u(h3A);                     ln_rc_u(h3B);
        } else {
            ln_tanh_g(hA, sg1, skb1);         ln_tanh_g(hB, sg1, skb1);
            gemm8(hA, h2A, sW2, sb2);         gemm8(hB, h2B, sW2, sb2);
            ln_tanh_g(h2A, sg2, skb2);        ln_tanh_g(h2B, sg2, skb2);
            gemm8(h2A, h3A, sW3, sb3);        gemm8(h2B, h3B, sW3, sb3);
            ln_rc_g(h3A, sg3, skb3);          ln_rc_g(h3B, sg3, skb3);
        }

        float dA = 0.0f, dB = 0.0f;
#pragma unroll
        for (int k = 0; k < 8; k++) {
            float w = sW4[k];
            dA = fmaf(h3A[k], w, dA);
            dB = fmaf(h3B[k], w, dB);
        }
        float oA = fmaf(-2.0f, dA, w4sum);
        float oB = fmaf(-2.0f, dB, w4sum);
        if (e + 1 < E) *(float2*)(out + e) = make_float2(oA, oB);
        else           out[e] = oA;

        // 4) rotate pipeline state
        if (!nv) break;
        As0 = pAs0; As1 = pAs1; Ab0 = pAb0; Ab1 = pAb1;
        Bs0 = pBs0; Bs1 = pBs1; Bb0 = pBb0; Bb1 = pBb1;
        ns0 = ms0; ns1 = ms1; nd0 = md0; nd1 = md1;
        e = en;
    }
}

// ---------------------------------------------------------------------------
extern "C" void kernel_launch(void* const* d_in, const int* in_sizes, int n_in,
                              void* d_out, int out_size)
{
    const float* x     = (const float*)d_in[0];
    const int*   ei    = (const int*)d_in[1];
    const float* vp    = (const float*)d_in[2];
    const int*   batch = (const int*)d_in[3];
    const float* W1  = (const float*)d_in[4];
    const float* b1  = (const float*)d_in[5];
    const float* g1  = (const float*)d_in[6];
    const float* be1 = (const float*)d_in[7];
    const float* W2  = (const float*)d_in[8];
    const float* b2  = (const float*)d_in[9];
    const float* g2  = (const float*)d_in[10];
    const float* be2 = (const float*)d_in[11];
    const float* W3  = (const float*)d_in[12];
    const float* b3  = (const float*)d_in[13];
    const float* g3  = (const float*)d_in[14];
    const float* be3 = (const float*)d_in[15];
    const float* W4  = (const float*)d_in[16];
    const float* b4  = (const float*)d_in[17];

    int N = in_sizes[0] / 16;
    int E = in_sizes[1] / 2;
    int G = in_sizes[2] / 16;

    int pb = (N + 255) / 256;
    pre_k<<<pb, 256>>>(x, batch, vp, W1, b1, ei, N, G);

    // persistent 1-wave grid: 4 blocks/SM x 148 SMs = 16 warps/SM
    int eb = 592;
    long long need = ((long long)E / 2 + 127) / 128;
    if (need < eb) eb = (int)(need > 0 ? need : 1);
    edge_k<<<eb, 128>>>(ei, E, g1, be1, W2, b2, g2, be2, W3, b3, g3, be3,
                        W4, b4, (float*)d_out);
}